// round 2
// baseline (speedup 1.0000x reference)
#include <cuda_runtime.h>
#include <math.h>

// Problem constants
#define TOK 8192      // B*S = 4*2048
#define HID 1024      // H
#define RNK 256       // R
#define FFN 4096      // F
#define NE  8         // experts
#define ERK (NE*RNK)  // 2048

// Scratch (device globals: allocation-free per harness rules)
__device__ float g_mw[TOK * NE];                 // 256 KB  router weights (masked softmax)
__device__ float g_t[(size_t)TOK * ERK];         // 64 MB   rank activations (scaled)
__device__ float g_h[(size_t)TOK * FFN];         // 128 MB  gelu(mixed)

// ---------------------------------------------------------------------------
// Router: one warp per token. logits = x @ router_w + b; softmax; top-2 mask.
// ---------------------------------------------------------------------------
__global__ void router_kernel(const float* __restrict__ x,
                              const float* __restrict__ rw,
                              const float* __restrict__ rb) {
    int warp = (blockIdx.x * blockDim.x + threadIdx.x) >> 5;
    int lane = threadIdx.x & 31;
    if (warp >= TOK) return;

    const float4* xr = reinterpret_cast<const float4*>(x + (size_t)warp * HID);
    float acc[NE];
#pragma unroll
    for (int e = 0; e < NE; e++) acc[e] = 0.f;

    // HID/4 = 256 float4 per token row; lane-strided
    for (int i = lane; i < HID / 4; i += 32) {
        float4 xv = xr[i];
        int h = i * 4;
        const float4* w0 = reinterpret_cast<const float4*>(rw + (size_t)h * NE);
        float4 a0 = w0[0], a1 = w0[1];   // row h   (8 floats)
        float4 b0 = w0[2], b1 = w0[3];   // row h+1
        float4 c0 = w0[4], c1 = w0[5];   // row h+2
        float4 d0 = w0[6], d1 = w0[7];   // row h+3
        acc[0] += xv.x*a0.x + xv.y*b0.x + xv.z*c0.x + xv.w*d0.x;
        acc[1] += xv.x*a0.y + xv.y*b0.y + xv.z*c0.y + xv.w*d0.y;
        acc[2] += xv.x*a0.z + xv.y*b0.z + xv.z*c0.z + xv.w*d0.z;
        acc[3] += xv.x*a0.w + xv.y*b0.w + xv.z*c0.w + xv.w*d0.w;
        acc[4] += xv.x*a1.x + xv.y*b1.x + xv.z*c1.x + xv.w*d1.x;
        acc[5] += xv.x*a1.y + xv.y*b1.y + xv.z*c1.y + xv.w*d1.y;
        acc[6] += xv.x*a1.z + xv.y*b1.z + xv.z*c1.z + xv.w*d1.z;
        acc[7] += xv.x*a1.w + xv.y*b1.w + xv.z*c1.w + xv.w*d1.w;
    }
#pragma unroll
    for (int e = 0; e < NE; e++) {
#pragma unroll
        for (int o = 16; o > 0; o >>= 1)
            acc[e] += __shfl_xor_sync(0xffffffffu, acc[e], o);
    }

    if (lane == 0) {
        float lg[NE];
        float m = -1e30f;
#pragma unroll
        for (int e = 0; e < NE; e++) { lg[e] = acc[e] + rb[e]; m = fmaxf(m, lg[e]); }
        float p[NE], s = 0.f;
#pragma unroll
        for (int e = 0; e < NE; e++) { p[e] = expf(lg[e] - m); s += p[e]; }
        float inv = 1.f / s;
        // top-2 (strict > keeps lowest index on ties, matching lax.top_k)
        int i0 = 0;
#pragma unroll
        for (int e = 1; e < NE; e++) if (p[e] > p[i0]) i0 = e;
        int i1 = (i0 == 0) ? 1 : 0;
#pragma unroll
        for (int e = 0; e < NE; e++) { if (e == i0) continue; if (p[e] > p[i1]) i1 = e; }
#pragma unroll
        for (int e = 0; e < NE; e++)
            g_mw[warp * NE + e] = (e == i0 || e == i1) ? p[e] * inv : 0.f;
    }
}

// ---------------------------------------------------------------------------
// Tiled SGEMM: C[M,N] = A[M,K] @ B[K,N], 128x128x8 tiles, 8x8 microtile.
// MODE 1: B = w1 viewed per-expert (ldb=RNK, base offset per tile),
//         epilogue scales row r by mw[r*NE + expert_of_tile]  -> writes g_t
// MODE 2: plain B (w2 as [2048,4096]), epilogue = exact gelu   -> writes g_h
// MODE 3: plain B (lin2_w), epilogue adds bias                 -> writes d_out
// All dims are multiples of tile sizes; no bounds checks.
// ---------------------------------------------------------------------------
#define BM 128
#define BN 128
#define BK 8
#define TM 8
#define TN 8

template <int MODE>
__global__ __launch_bounds__(256)
void sgemm_kernel(const float* __restrict__ A, int lda, int Kdim,
                  const float* __restrict__ Bsrc,
                  float* __restrict__ C, int ldc,
                  const float* __restrict__ extra) {
    __shared__ float As[BK][BM];
    __shared__ float Bs[BK][BN];

    const int tid = threadIdx.x;
    const int n0 = blockIdx.x * BN;
    const int m0 = blockIdx.y * BM;

    const float* Bptr;
    int ldb;
    int eIdx = 0;
    if (MODE == 1) {
        eIdx = n0 >> 8;                                   // expert of this tile
        ldb  = RNK;
        Bptr = Bsrc + (size_t)eIdx * HID * RNK + (n0 & (RNK - 1));
    } else if (MODE == 2) {
        ldb = FFN;  Bptr = Bsrc + n0;
    } else {
        ldb = HID;  Bptr = Bsrc + n0;
    }

    const int aRow = tid >> 1;            // 0..127
    const int aCol = (tid & 1) * 4;       // 0 or 4
    const int bRow = tid >> 5;            // 0..7
    const int bCol = (tid & 31) * 4;      // 0..124
    const int tx = tid & 15, ty = tid >> 4;

    const float* Atile = A + (size_t)m0 * lda;

    float acc[TM][TN];
#pragma unroll
    for (int i = 0; i < TM; i++)
#pragma unroll
        for (int j = 0; j < TN; j++) acc[i][j] = 0.f;

    float ra[TM], rb[TN];

    for (int k0 = 0; k0 < Kdim; k0 += BK) {
        float4 av = *reinterpret_cast<const float4*>(Atile + (size_t)aRow * lda + k0 + aCol);
        As[aCol + 0][aRow] = av.x;
        As[aCol + 1][aRow] = av.y;
        As[aCol + 2][aRow] = av.z;
        As[aCol + 3][aRow] = av.w;
        float4 bv = *reinterpret_cast<const float4*>(Bptr + (size_t)(k0 + bRow) * ldb + bCol);
        *reinterpret_cast<float4*>(&Bs[bRow][bCol]) = bv;
        __syncthreads();

#pragma unroll
        for (int kk = 0; kk < BK; kk++) {
#pragma unroll
            for (int i = 0; i < TM; i += 4)
                *reinterpret_cast<float4*>(&ra[i]) =
                    *reinterpret_cast<const float4*>(&As[kk][ty * TM + i]);
#pragma unroll
            for (int j = 0; j < TN; j += 4)
                *reinterpret_cast<float4*>(&rb[j]) =
                    *reinterpret_cast<const float4*>(&Bs[kk][tx * TN + j]);
#pragma unroll
            for (int i = 0; i < TM; i++)
#pragma unroll
                for (int j = 0; j < TN; j++)
                    acc[i][j] += ra[i] * rb[j];
        }
        __syncthreads();
    }

    // Epilogue
#pragma unroll
    for (int i = 0; i < TM; i++) {
        const int row = m0 + ty * TM + i;
        float s = 1.f;
        if (MODE == 1) s = extra[row * NE + eIdx];  // mw scale (0 for non-top2)
#pragma unroll
        for (int jj = 0; jj < TN; jj += 4) {
            const int col = n0 + tx * TN + jj;
            float4 v;
            v.x = acc[i][jj + 0];
            v.y = acc[i][jj + 1];
            v.z = acc[i][jj + 2];
            v.w = acc[i][jj + 3];
            if (MODE == 1) {
                v.x *= s; v.y *= s; v.z *= s; v.w *= s;
            } else if (MODE == 2) {
                // exact (erf) gelu
                v.x = 0.5f * v.x * (1.f + erff(v.x * 0.70710678118654752f));
                v.y = 0.5f * v.y * (1.f + erff(v.y * 0.70710678118654752f));
                v.z = 0.5f * v.z * (1.f + erff(v.z * 0.70710678118654752f));
                v.w = 0.5f * v.w * (1.f + erff(v.w * 0.70710678118654752f));
            } else {
                v.x += extra[col + 0];
                v.y += extra[col + 1];
                v.z += extra[col + 2];
                v.w += extra[col + 3];
            }
            *reinterpret_cast<float4*>(C + (size_t)row * ldc + col) = v;
        }
    }
}

// ---------------------------------------------------------------------------
extern "C" void kernel_launch(void* const* d_in, const int* in_sizes, int n_in,
                              void* d_out, int out_size) {
    const float* x        = (const float*)d_in[0];  // [B,S,H]  -> [8192,1024]
    const float* router_w = (const float*)d_in[1];  // [H,E]
    const float* router_b = (const float*)d_in[2];  // [E]
    const float* w1       = (const float*)d_in[3];  // [E,H,R]
    const float* w2       = (const float*)d_in[4];  // [E,R,F]  == [2048,4096]
    const float* lin2_w   = (const float*)d_in[5];  // [F,H]
    const float* lin2_b   = (const float*)d_in[6];  // [H]
    float* out = (float*)d_out;                     // [8192,1024]

    float *mw_ptr, *t_ptr, *h_ptr;
    cudaGetSymbolAddress((void**)&mw_ptr, g_mw);
    cudaGetSymbolAddress((void**)&t_ptr,  g_t);
    cudaGetSymbolAddress((void**)&h_ptr,  g_h);

    // Router: 1 warp/token
    router_kernel<<<TOK / 8, 256>>>(x, router_w, router_b);

    // Stage 1: t = (x @ w1[e]) * mw      [8192,1024] x [1024,2048]
    sgemm_kernel<1><<<dim3(ERK / BN, TOK / BM), 256>>>(x, HID, HID, w1, t_ptr, ERK, mw_ptr);

    // Stage 2: h = gelu(t @ w2flat)      [8192,2048] x [2048,4096]
    sgemm_kernel<2><<<dim3(FFN / BN, TOK / BM), 256>>>(t_ptr, ERK, ERK, w2, h_ptr, FFN, nullptr);

    // Stage 3: out = h @ lin2_w + b      [8192,4096] x [4096,1024]
    sgemm_kernel<3><<<dim3(HID / BN, TOK / BM), 256>>>(h_ptr, FFN, FFN, lin2_w, out, HID, lin2_b);
}

// round 5
// speedup vs baseline: 4.3984x; 4.3984x over previous
#include <cuda_runtime.h>
#include <cuda_bf16.h>
#include <stdint.h>
#include <math.h>

// Problem constants
#define TOK 8192
#define HID 1024
#define RNK 256
#define FFN 4096
#define NE  8
#define ERK (NE*RNK)  // 2048

// GEMM tiling
#define BM 128
#define BN 128
#define BK 32
#define NTHREADS 256
#define ROWB 80                  // padded row bytes (32 bf16 = 64B + 16B pad)
#define TILEB (128*ROWB)         // 10240 B per tile
#define STAGEB (4*TILEB)         // Ah Al Bh Bl = 40960 B
#define SMEM_BYTES (2*STAGEB)    // 81920 B

// ---------------------------------------------------------------------------
// Scratch (device globals — allocation-free)
// ---------------------------------------------------------------------------
__device__ float g_mw[TOK * NE];
__device__ __nv_bfloat16 g_xh[(size_t)TOK * HID], g_xl[(size_t)TOK * HID];
__device__ __nv_bfloat16 g_th[(size_t)TOK * ERK], g_tl[(size_t)TOK * ERK];
__device__ __nv_bfloat16 g_hh[(size_t)TOK * FFN], g_hl[(size_t)TOK * FFN];
__device__ __nv_bfloat16 g_w1h[(size_t)ERK * HID], g_w1l[(size_t)ERK * HID];
__device__ __nv_bfloat16 g_w2h[(size_t)FFN * ERK], g_w2l[(size_t)FFN * ERK];
__device__ __nv_bfloat16 g_w3h[(size_t)HID * FFN], g_w3l[(size_t)HID * FFN];

// ---------------------------------------------------------------------------
// PTX helpers (base sm_103 target — NO tcgen05)
// ---------------------------------------------------------------------------
__device__ __forceinline__ uint32_t s2u(const void* p) {
    uint32_t a;
    asm("{ .reg .u64 t; cvta.to.shared.u64 t, %1; cvt.u32.u64 %0, t; }" : "=r"(a) : "l"(p));
    return a;
}

__device__ __forceinline__ void cp16(uint32_t dst, const void* src) {
    asm volatile("cp.async.cg.shared.global [%0], [%1], 16;" :: "r"(dst), "l"(src) : "memory");
}
__device__ __forceinline__ void cp_commit() {
    asm volatile("cp.async.commit_group;" ::: "memory");
}
template <int N>
__device__ __forceinline__ void cp_wait() {
    asm volatile("cp.async.wait_group %0;" :: "n"(N) : "memory");
}

__device__ __forceinline__ void ldsm4(uint32_t* r, uint32_t addr) {
    asm volatile("ldmatrix.sync.aligned.m8n8.x4.shared.b16 {%0,%1,%2,%3}, [%4];"
                 : "=r"(r[0]), "=r"(r[1]), "=r"(r[2]), "=r"(r[3]) : "r"(addr));
}

__device__ __forceinline__ void mma16816(float* c, const uint32_t* a, const uint32_t* b) {
    asm volatile(
        "mma.sync.aligned.m16n8k16.row.col.f32.bf16.bf16.f32 "
        "{%0,%1,%2,%3}, {%4,%5,%6,%7}, {%8,%9}, {%0,%1,%2,%3};"
        : "+f"(c[0]), "+f"(c[1]), "+f"(c[2]), "+f"(c[3])
        : "r"(a[0]), "r"(a[1]), "r"(a[2]), "r"(a[3]), "r"(b[0]), "r"(b[1]));
}

__device__ __forceinline__ void split_bf16(float v, __nv_bfloat16& hi, __nv_bfloat16& lo) {
    hi = __float2bfloat16(v);
    lo = __float2bfloat16(v - __bfloat162float(hi));
}

// ---------------------------------------------------------------------------
// Router: one warp per token
// ---------------------------------------------------------------------------
__global__ void router_kernel(const float* __restrict__ x,
                              const float* __restrict__ rw,
                              const float* __restrict__ rb) {
    int warp = (blockIdx.x * blockDim.x + threadIdx.x) >> 5;
    int lane = threadIdx.x & 31;
    if (warp >= TOK) return;

    const float4* xr = reinterpret_cast<const float4*>(x + (size_t)warp * HID);
    float acc[NE];
#pragma unroll
    for (int e = 0; e < NE; e++) acc[e] = 0.f;

    for (int i = lane; i < HID / 4; i += 32) {
        float4 xv = xr[i];
        int h = i * 4;
        const float4* w0 = reinterpret_cast<const float4*>(rw + (size_t)h * NE);
        float4 a0 = w0[0], a1 = w0[1];
        float4 b0 = w0[2], b1 = w0[3];
        float4 c0 = w0[4], c1 = w0[5];
        float4 d0 = w0[6], d1 = w0[7];
        acc[0] += xv.x*a0.x + xv.y*b0.x + xv.z*c0.x + xv.w*d0.x;
        acc[1] += xv.x*a0.y + xv.y*b0.y + xv.z*c0.y + xv.w*d0.y;
        acc[2] += xv.x*a0.z + xv.y*b0.z + xv.z*c0.z + xv.w*d0.z;
        acc[3] += xv.x*a0.w + xv.y*b0.w + xv.z*c0.w + xv.w*d0.w;
        acc[4] += xv.x*a1.x + xv.y*b1.x + xv.z*c1.x + xv.w*d1.x;
        acc[5] += xv.x*a1.y + xv.y*b1.y + xv.z*c1.y + xv.w*d1.y;
        acc[6] += xv.x*a1.z + xv.y*b1.z + xv.z*c1.z + xv.w*d1.z;
        acc[7] += xv.x*a1.w + xv.y*b1.w + xv.z*c1.w + xv.w*d1.w;
    }
#pragma unroll
    for (int e = 0; e < NE; e++) {
#pragma unroll
        for (int o = 16; o > 0; o >>= 1)
            acc[e] += __shfl_xor_sync(0xffffffffu, acc[e], o);
    }
    if (lane == 0) {
        float lg[NE], m = -1e30f;
#pragma unroll
        for (int e = 0; e < NE; e++) { lg[e] = acc[e] + rb[e]; m = fmaxf(m, lg[e]); }
        float p[NE], s = 0.f;
#pragma unroll
        for (int e = 0; e < NE; e++) { p[e] = expf(lg[e] - m); s += p[e]; }
        float inv = 1.f / s;
        int i0 = 0;
#pragma unroll
        for (int e = 1; e < NE; e++) if (p[e] > p[i0]) i0 = e;
        int i1 = (i0 == 0) ? 1 : 0;
#pragma unroll
        for (int e = 0; e < NE; e++) { if (e == i0) continue; if (p[e] > p[i1]) i1 = e; }
#pragma unroll
        for (int e = 0; e < NE; e++)
            g_mw[warp * NE + e] = (e == i0 || e == i1) ? p[e] * inv : 0.f;
    }
}

// ---------------------------------------------------------------------------
// x -> (hi, lo) bf16 split
// ---------------------------------------------------------------------------
__global__ void convert_x_kernel(const float* __restrict__ x,
                                 __nv_bfloat16* __restrict__ xh,
                                 __nv_bfloat16* __restrict__ xl) {
    size_t i = (size_t)blockIdx.x * blockDim.x + threadIdx.x;
    float4 v = reinterpret_cast<const float4*>(x)[i];
    __nv_bfloat16 h0, h1, h2, h3, l0, l1, l2, l3;
    split_bf16(v.x, h0, l0); split_bf16(v.y, h1, l1);
    split_bf16(v.z, h2, l2); split_bf16(v.w, h3, l3);
    __nv_bfloat162* ph = reinterpret_cast<__nv_bfloat162*>(xh) + 2 * i;
    __nv_bfloat162* pl = reinterpret_cast<__nv_bfloat162*>(xl) + 2 * i;
    __nv_bfloat162 a; a.x = h0; a.y = h1; ph[0] = a;
    __nv_bfloat162 b; b.x = h2; b.y = h3; ph[1] = b;
    __nv_bfloat162 c; c.x = l0; c.y = l1; pl[0] = c;
    __nv_bfloat162 d; d.x = l2; d.y = l3; pl[1] = d;
}

// ---------------------------------------------------------------------------
// Weight transpose + split: W[K,N] fp32 -> Oh/Ol[N,K] bf16
// ---------------------------------------------------------------------------
__global__ void convert_w_kernel(const float* __restrict__ W,
                                 __nv_bfloat16* __restrict__ Oh,
                                 __nv_bfloat16* __restrict__ Ol,
                                 int K, int N, size_t wStride, size_t oStride) {
    __shared__ float t[32][33];
    const float* Wb = W + (size_t)blockIdx.z * wStride;
    __nv_bfloat16* oh = Oh + (size_t)blockIdx.z * oStride;
    __nv_bfloat16* ol = Ol + (size_t)blockIdx.z * oStride;
    int k0 = blockIdx.y * 32, n0 = blockIdx.x * 32;
    int tx = threadIdx.x, ty = threadIdx.y;
#pragma unroll
    for (int j = 0; j < 4; j++)
        t[ty + 8 * j][tx] = Wb[(size_t)(k0 + ty + 8 * j) * N + n0 + tx];
    __syncthreads();
#pragma unroll
    for (int j = 0; j < 4; j++) {
        int r = ty + 8 * j;
        float v = t[tx][r];
        __nv_bfloat16 hi, lo; split_bf16(v, hi, lo);
        size_t o = (size_t)(n0 + r) * K + k0 + tx;
        oh[o] = hi; ol[o] = lo;
    }
}

// ---------------------------------------------------------------------------
// mma.sync GEMM: C[M,N] = A[M,K] * B[N,K]^T, 2-term bf16 split, fp32 accum.
// MODE 1: *mw          -> bf16 hi/lo     MODE 2: gelu -> bf16 hi/lo
// MODE 3: +bias        -> fp32
// ---------------------------------------------------------------------------
template <int MODE>
__global__ void __launch_bounds__(NTHREADS, 2)
mma_gemm(const __nv_bfloat16* __restrict__ Ah, const __nv_bfloat16* __restrict__ Al,
         const __nv_bfloat16* __restrict__ Bh, const __nv_bfloat16* __restrict__ Bl,
         int Kd,
         __nv_bfloat16* __restrict__ Ch, __nv_bfloat16* __restrict__ Cl,
         float* __restrict__ Cf, int ldc,
         const float* __restrict__ extra) {
    extern __shared__ __align__(128) char smem[];
    const uint32_t sbase = s2u(smem);
    const int tid = threadIdx.x;
    const int lane = tid & 31;
    const int wid = tid >> 5;
    const int wm = wid & 3;           // 4 warps over M (32 rows each)
    const int wn = wid >> 2;          // 2 warps over N (64 cols each)
    const int m0 = blockIdx.y * BM;
    const int n0 = blockIdx.x * BN;

    float acc[2][8][4];
#pragma unroll
    for (int i = 0; i < 2; i++)
#pragma unroll
        for (int j = 0; j < 8; j++)
#pragma unroll
            for (int k = 0; k < 4; k++) acc[i][j][k] = 0.f;

    // per-thread load slots: idx in {tid, tid+256}; r=idx>>2 (row), q=idx&3 (16B col)
    const int r0s = tid >> 2, q0 = (tid & 3);
    const int r1s = r0s + 64;

    const int nc = Kd / BK;

    // prologue: chunk 0 -> stage 0
    {
        const size_t kOff = 0;
#pragma unroll
        for (int t2 = 0; t2 < 2; t2++) {
            int r = (t2 == 0) ? r0s : r1s;
            uint32_t d = sbase + (uint32_t)(r * ROWB + q0 * 16);
            size_t ga = (size_t)(m0 + r) * Kd + kOff + q0 * 8;
            size_t gb = (size_t)(n0 + r) * Kd + kOff + q0 * 8;
            cp16(d,             Ah + ga);
            cp16(d + TILEB,     Al + ga);
            cp16(d + 2*TILEB,   Bh + gb);
            cp16(d + 3*TILEB,   Bl + gb);
        }
        cp_commit();
    }

    const int g = lane >> 3, lr = lane & 7;

    for (int c = 0; c < nc; c++) {
        const int st = c & 1;
        if (c + 1 < nc) {
            const uint32_t s1 = sbase + (uint32_t)((st ^ 1) * STAGEB);
            const size_t kOff = (size_t)(c + 1) * BK;
#pragma unroll
            for (int t2 = 0; t2 < 2; t2++) {
                int r = (t2 == 0) ? r0s : r1s;
                uint32_t d = s1 + (uint32_t)(r * ROWB + q0 * 16);
                size_t ga = (size_t)(m0 + r) * Kd + kOff + q0 * 8;
                size_t gb = (size_t)(n0 + r) * Kd + kOff + q0 * 8;
                cp16(d,           Ah + ga);
                cp16(d + TILEB,   Al + ga);
                cp16(d + 2*TILEB, Bh + gb);
                cp16(d + 3*TILEB, Bl + gb);
            }
            cp_commit();
            cp_wait<1>();
        } else {
            cp_wait<0>();
        }
        __syncthreads();

        const uint32_t s0 = sbase + (uint32_t)(st * STAGEB);
#pragma unroll
        for (int ks = 0; ks < 2; ks++) {
            uint32_t afh[2][4], afl[2][4];
#pragma unroll
            for (int mt = 0; mt < 2; mt++) {
                int row = wm * 32 + mt * 16 + (g & 1) * 8 + lr;
                uint32_t addr = s0 + (uint32_t)(row * ROWB + ks * 32 + (g >> 1) * 16);
                ldsm4(afh[mt], addr);
                ldsm4(afl[mt], addr + TILEB);
            }
#pragma unroll
            for (int np = 0; np < 4; np++) {
                uint32_t bfh[4], bfl[4];
                int row = wn * 64 + np * 16 + (g >> 1) * 8 + lr;
                uint32_t addr = s0 + (uint32_t)(2*TILEB + row * ROWB + ks * 32 + (g & 1) * 16);
                ldsm4(bfh, addr);
                ldsm4(bfl, addr + TILEB);
#pragma unroll
                for (int mt = 0; mt < 2; mt++) {
#pragma unroll
                    for (int h2 = 0; h2 < 2; h2++) {
                        float* cc = acc[mt][np * 2 + h2];
                        mma16816(cc, afh[mt], bfh + h2 * 2);
                        mma16816(cc, afh[mt], bfl + h2 * 2);
                        mma16816(cc, afl[mt], bfh + h2 * 2);
                    }
                }
            }
        }
        __syncthreads();
    }

    // Epilogue
#pragma unroll
    for (int mt = 0; mt < 2; mt++) {
#pragma unroll
        for (int half = 0; half < 2; half++) {
            const int row = m0 + wm * 32 + mt * 16 + half * 8 + (lane >> 2);
            float s = 1.f;
            if (MODE == 1) s = extra[(size_t)row * NE + (blockIdx.x >> 1)];
            const size_t rbase = (size_t)row * ldc;
#pragma unroll
            for (int nt = 0; nt < 8; nt++) {
                const int col = n0 + wn * 64 + nt * 8 + (lane & 3) * 2;
                float v0 = acc[mt][nt][half * 2 + 0];
                float v1 = acc[mt][nt][half * 2 + 1];
                if (MODE == 3) {
                    float2 o;
                    o.x = v0 + extra[col];
                    o.y = v1 + extra[col + 1];
                    *reinterpret_cast<float2*>(Cf + rbase + col) = o;
                } else {
                    if (MODE == 1) { v0 *= s; v1 *= s; }
                    else {
                        v0 = 0.5f * v0 * (1.f + erff(v0 * 0.70710678118654752f));
                        v1 = 0.5f * v1 * (1.f + erff(v1 * 0.70710678118654752f));
                    }
                    __nv_bfloat16 h0, h1, l0, l1;
                    split_bf16(v0, h0, l0); split_bf16(v1, h1, l1);
                    __nv_bfloat162 hp; hp.x = h0; hp.y = h1;
                    __nv_bfloat162 lp; lp.x = l0; lp.y = l1;
                    *reinterpret_cast<__nv_bfloat162*>(Ch + rbase + col) = hp;
                    *reinterpret_cast<__nv_bfloat162*>(Cl + rbase + col) = lp;
                }
            }
        }
    }
}

// ---------------------------------------------------------------------------
extern "C" void kernel_launch(void* const* d_in, const int* in_sizes, int n_in,
                              void* d_out, int out_size) {
    const float* x        = (const float*)d_in[0];
    const float* router_w = (const float*)d_in[1];
    const float* router_b = (const float*)d_in[2];
    const float* w1       = (const float*)d_in[3];  // [E,H,R]
    const float* w2       = (const float*)d_in[4];  // [E,R,F] == [2048,4096]
    const float* lin2_w   = (const float*)d_in[5];  // [F,H]
    const float* lin2_b   = (const float*)d_in[6];  // [H]
    float* out = (float*)d_out;

    float* mw_p;
    __nv_bfloat16 *xh, *xl, *th, *tl, *hh, *hl, *w1h, *w1l, *w2h, *w2l, *w3h, *w3l;
    cudaGetSymbolAddress((void**)&mw_p, g_mw);
    cudaGetSymbolAddress((void**)&xh, g_xh);  cudaGetSymbolAddress((void**)&xl, g_xl);
    cudaGetSymbolAddress((void**)&th, g_th);  cudaGetSymbolAddress((void**)&tl, g_tl);
    cudaGetSymbolAddress((void**)&hh, g_hh);  cudaGetSymbolAddress((void**)&hl, g_hl);
    cudaGetSymbolAddress((void**)&w1h, g_w1h); cudaGetSymbolAddress((void**)&w1l, g_w1l);
    cudaGetSymbolAddress((void**)&w2h, g_w2h); cudaGetSymbolAddress((void**)&w2l, g_w2l);
    cudaGetSymbolAddress((void**)&w3h, g_w3h); cudaGetSymbolAddress((void**)&w3l, g_w3l);

    cudaFuncSetAttribute(mma_gemm<1>, cudaFuncAttributeMaxDynamicSharedMemorySize, SMEM_BYTES);
    cudaFuncSetAttribute(mma_gemm<2>, cudaFuncAttributeMaxDynamicSharedMemorySize, SMEM_BYTES);
    cudaFuncSetAttribute(mma_gemm<3>, cudaFuncAttributeMaxDynamicSharedMemorySize, SMEM_BYTES);

    // Router + conversions
    router_kernel<<<TOK / 8, 256>>>(x, router_w, router_b);
    convert_x_kernel<<<(TOK * HID / 4) / 256, 256>>>(x, xh, xl);
    convert_w_kernel<<<dim3(RNK / 32, HID / 32, NE), dim3(32, 8)>>>(
        w1, w1h, w1l, HID, RNK, (size_t)HID * RNK, (size_t)RNK * HID);
    convert_w_kernel<<<dim3(FFN / 32, ERK / 32, 1), dim3(32, 8)>>>(
        w2, w2h, w2l, ERK, FFN, 0, 0);
    convert_w_kernel<<<dim3(HID / 32, FFN / 32, 1), dim3(32, 8)>>>(
        lin2_w, w3h, w3l, FFN, HID, 0, 0);

    // Stage 1: t = (x @ w1[e]) * mw   [8192,1024]x[1024,2048]
    mma_gemm<1><<<dim3(ERK / BN, TOK / BM), NTHREADS, SMEM_BYTES>>>(
        xh, xl, w1h, w1l, HID, th, tl, nullptr, ERK, mw_p);
    // Stage 2: h = gelu(t @ w2)       [8192,2048]x[2048,4096]
    mma_gemm<2><<<dim3(FFN / BN, TOK / BM), NTHREADS, SMEM_BYTES>>>(
        th, tl, w2h, w2l, ERK, hh, hl, nullptr, FFN, nullptr);
    // Stage 3: out = h @ lin2 + b     [8192,4096]x[4096,1024]
    mma_gemm<3><<<dim3(HID / BN, TOK / BM), NTHREADS, SMEM_BYTES>>>(
        hh, hl, w3h, w3l, FFN, nullptr, nullptr, out, HID, lin2_b);
}

// round 7
// speedup vs baseline: 7.6592x; 1.7413x over previous
#include <cuda_runtime.h>
#include <cuda_bf16.h>
#include <stdint.h>
#include <math.h>

#define TOK 8192
#define HID 1024
#define RNK 256
#define FFN 4096
#define NE  8
#define ERK (NE*RNK)  // 2048
#define NPAIR 28
#define MAXT1 136     // <= 16384/128 + 8
#define MAXT2 92      // <= 8192/128 + 28

#define NTHREADS 256
#define ROWB 80
#define TILEB (128*ROWB)
#define STAGEB (4*TILEB)
#define SMEM_BYTES (2*STAGEB)

// ---------------------------------------------------------------------------
// Scratch (device globals)
// ---------------------------------------------------------------------------
__device__ float g_mw[TOK * NE];
__device__ int g_e0t[TOK], g_e1t[TOK], g_pidt[TOK];
__device__ int g_pcnt[NPAIR], g_poff[NPAIR], g_pfill[NPAIR], g_ptok[TOK];
__device__ int g_ecnt[NE], g_eoff[NE], g_efill[NE], g_etok[2 * TOK];
__device__ int g_t1grp[MAXT1], g_t1row[MAXT1];
__device__ int g_t2grp[MAXT2], g_t2row[MAXT2];
__device__ int g_pe0[NPAIR], g_pe1[NPAIR];
__device__ int g_meta[2];

__device__ __nv_bfloat16 g_xh[(size_t)TOK * HID], g_xl[(size_t)TOK * HID];
__device__ __nv_bfloat16 g_th[(size_t)TOK * ERK], g_tl[(size_t)TOK * ERK];
__device__ __nv_bfloat16 g_hh[(size_t)TOK * FFN], g_hl[(size_t)TOK * FFN];
__device__ __nv_bfloat16 g_w1h[(size_t)ERK * HID], g_w1l[(size_t)ERK * HID];
__device__ __nv_bfloat16 g_w2h[(size_t)FFN * ERK], g_w2l[(size_t)FFN * ERK];
__device__ __nv_bfloat16 g_w3h[(size_t)HID * FFN], g_w3l[(size_t)HID * FFN];

// ---------------------------------------------------------------------------
// PTX helpers (base sm_103 target)
// ---------------------------------------------------------------------------
__device__ __forceinline__ uint32_t s2u(const void* p) {
    uint32_t a;
    asm("{ .reg .u64 t; cvta.to.shared.u64 t, %1; cvt.u32.u64 %0, t; }" : "=r"(a) : "l"(p));
    return a;
}
__device__ __forceinline__ void cp16(uint32_t dst, const void* src) {
    asm volatile("cp.async.cg.shared.global [%0], [%1], 16;" :: "r"(dst), "l"(src) : "memory");
}
__device__ __forceinline__ void cp_commit() {
    asm volatile("cp.async.commit_group;" ::: "memory");
}
template <int N>
__device__ __forceinline__ void cp_wait() {
    asm volatile("cp.async.wait_group %0;" :: "n"(N) : "memory");
}
__device__ __forceinline__ void ldsm4(uint32_t* r, uint32_t addr) {
    asm volatile("ldmatrix.sync.aligned.m8n8.x4.shared.b16 {%0,%1,%2,%3}, [%4];"
                 : "=r"(r[0]), "=r"(r[1]), "=r"(r[2]), "=r"(r[3]) : "r"(addr));
}
__device__ __forceinline__ void mma16816(float* c, const uint32_t* a, const uint32_t* b) {
    asm volatile(
        "mma.sync.aligned.m16n8k16.row.col.f32.bf16.bf16.f32 "
        "{%0,%1,%2,%3}, {%4,%5,%6,%7}, {%8,%9}, {%0,%1,%2,%3};"
        : "+f"(c[0]), "+f"(c[1]), "+f"(c[2]), "+f"(c[3])
        : "r"(a[0]), "r"(a[1]), "r"(a[2]), "r"(a[3]), "r"(b[0]), "r"(b[1]));
}
__device__ __forceinline__ void split_bf16(float v, __nv_bfloat16& hi, __nv_bfloat16& lo) {
    hi = __float2bfloat16(v);
    lo = __float2bfloat16(v - __bfloat162float(hi));
}

// ---------------------------------------------------------------------------
// Routing infrastructure
// ---------------------------------------------------------------------------
__global__ void zero_kernel() {
    int i = threadIdx.x;
    if (i < NPAIR) { g_pcnt[i] = 0; g_pfill[i] = 0; }
    if (i < NE)    { g_ecnt[i] = 0; g_efill[i] = 0; }
}

__global__ void router_kernel(const float* __restrict__ x,
                              const float* __restrict__ rw,
                              const float* __restrict__ rb) {
    int warp = (blockIdx.x * blockDim.x + threadIdx.x) >> 5;
    int lane = threadIdx.x & 31;
    if (warp >= TOK) return;

    const float4* xr = reinterpret_cast<const float4*>(x + (size_t)warp * HID);
    float acc[NE];
#pragma unroll
    for (int e = 0; e < NE; e++) acc[e] = 0.f;

    for (int i = lane; i < HID / 4; i += 32) {
        float4 xv = xr[i];
        int h = i * 4;
        const float4* w0 = reinterpret_cast<const float4*>(rw + (size_t)h * NE);
        float4 a0 = w0[0], a1 = w0[1];
        float4 b0 = w0[2], b1 = w0[3];
        float4 c0 = w0[4], c1 = w0[5];
        float4 d0 = w0[6], d1 = w0[7];
        acc[0] += xv.x*a0.x + xv.y*b0.x + xv.z*c0.x + xv.w*d0.x;
        acc[1] += xv.x*a0.y + xv.y*b0.y + xv.z*c0.y + xv.w*d0.y;
        acc[2] += xv.x*a0.z + xv.y*b0.z + xv.z*c0.z + xv.w*d0.z;
        acc[3] += xv.x*a0.w + xv.y*b0.w + xv.z*c0.w + xv.w*d0.w;
        acc[4] += xv.x*a1.x + xv.y*b1.x + xv.z*c1.x + xv.w*d1.x;
        acc[5] += xv.x*a1.y + xv.y*b1.y + xv.z*c1.y + xv.w*d1.y;
        acc[6] += xv.x*a1.z + xv.y*b1.z + xv.z*c1.z + xv.w*d1.z;
        acc[7] += xv.x*a1.w + xv.y*b1.w + xv.z*c1.w + xv.w*d1.w;
    }
#pragma unroll
    for (int e = 0; e < NE; e++) {
#pragma unroll
        for (int o = 16; o > 0; o >>= 1)
            acc[e] += __shfl_xor_sync(0xffffffffu, acc[e], o);
    }
    if (lane == 0) {
        float lg[NE], m = -1e30f;
#pragma unroll
        for (int e = 0; e < NE; e++) { lg[e] = acc[e] + rb[e]; m = fmaxf(m, lg[e]); }
        float p[NE], s = 0.f;
#pragma unroll
        for (int e = 0; e < NE; e++) { p[e] = expf(lg[e] - m); s += p[e]; }
        float inv = 1.f / s;
        int i0 = 0;
#pragma unroll
        for (int e = 1; e < NE; e++) if (p[e] > p[i0]) i0 = e;
        int i1 = (i0 == 0) ? 1 : 0;
#pragma unroll
        for (int e = 0; e < NE; e++) { if (e == i0) continue; if (p[e] > p[i1]) i1 = e; }
#pragma unroll
        for (int e = 0; e < NE; e++)
            g_mw[warp * NE + e] = (e == i0 || e == i1) ? p[e] * inv : 0.f;
        int e0 = min(i0, i1), e1 = max(i0, i1);
        int pid = e0 * (2 * NE - e0 - 1) / 2 + (e1 - e0 - 1);
        g_e0t[warp] = e0; g_e1t[warp] = e1; g_pidt[warp] = pid;
        atomicAdd(&g_pcnt[pid], 1);
        atomicAdd(&g_ecnt[e0], 1);
        atomicAdd(&g_ecnt[e1], 1);
    }
}

__global__ void plan_kernel() {
    if (threadIdx.x != 0) return;
    int off = 0, nt = 0;
    for (int e = 0; e < NE; e++) {
        g_eoff[e] = off;
        for (int r = 0; r < g_ecnt[e]; r += 128) { g_t1grp[nt] = e; g_t1row[nt] = r; nt++; }
        off += g_ecnt[e];
    }
    g_meta[0] = nt;
    off = 0; nt = 0;
    int p = 0;
    for (int a = 0; a < NE; a++)
        for (int b = a + 1; b < NE; b++) {
            g_pe0[p] = a; g_pe1[p] = b;
            g_poff[p] = off;
            for (int r = 0; r < g_pcnt[p]; r += 128) { g_t2grp[nt] = p; g_t2row[nt] = r; nt++; }
            off += g_pcnt[p];
            p++;
        }
    g_meta[1] = nt;
}

__global__ void scatter_kernel() {
    int t = blockIdx.x * blockDim.x + threadIdx.x;
    if (t >= TOK) return;
    int pid = g_pidt[t];
    int pos = atomicAdd(&g_pfill[pid], 1);
    g_ptok[g_poff[pid] + pos] = t;
    int e0 = g_e0t[t], e1 = g_e1t[t];
    pos = atomicAdd(&g_efill[e0], 1); g_etok[g_eoff[e0] + pos] = t;
    pos = atomicAdd(&g_efill[e1], 1); g_etok[g_eoff[e1] + pos] = t;
}

// ---------------------------------------------------------------------------
// Conversions
// ---------------------------------------------------------------------------
__global__ void convert_x_kernel(const float* __restrict__ x,
                                 __nv_bfloat16* __restrict__ xh,
                                 __nv_bfloat16* __restrict__ xl) {
    size_t i = (size_t)blockIdx.x * blockDim.x + threadIdx.x;
    float4 v = reinterpret_cast<const float4*>(x)[i];
    __nv_bfloat16 h0, h1, h2, h3, l0, l1, l2, l3;
    split_bf16(v.x, h0, l0); split_bf16(v.y, h1, l1);
    split_bf16(v.z, h2, l2); split_bf16(v.w, h3, l3);
    __nv_bfloat162* ph = reinterpret_cast<__nv_bfloat162*>(xh) + 2 * i;
    __nv_bfloat162* pl = reinterpret_cast<__nv_bfloat162*>(xl) + 2 * i;
    __nv_bfloat162 a; a.x = h0; a.y = h1; ph[0] = a;
    __nv_bfloat162 b; b.x = h2; b.y = h3; ph[1] = b;
    __nv_bfloat162 c; c.x = l0; c.y = l1; pl[0] = c;
    __nv_bfloat162 d; d.x = l2; d.y = l3; pl[1] = d;
}

__global__ void convert_w_kernel(const float* __restrict__ W,
                                 __nv_bfloat16* __restrict__ Oh,
                                 __nv_bfloat16* __restrict__ Ol,
                                 int K, int N, size_t wStride, size_t oStride) {
    __shared__ float t[32][33];
    const float* Wb = W + (size_t)blockIdx.z * wStride;
    __nv_bfloat16* oh = Oh + (size_t)blockIdx.z * oStride;
    __nv_bfloat16* ol = Ol + (size_t)blockIdx.z * oStride;
    int k0 = blockIdx.y * 32, n0 = blockIdx.x * 32;
    int tx = threadIdx.x, ty = threadIdx.y;
#pragma unroll
    for (int j = 0; j < 4; j++)
        t[ty + 8 * j][tx] = Wb[(size_t)(k0 + ty + 8 * j) * N + n0 + tx];
    __syncthreads();
#pragma unroll
    for (int j = 0; j < 4; j++) {
        int r = ty + 8 * j;
        float v = t[tx][r];
        __nv_bfloat16 hi, lo; split_bf16(v, hi, lo);
        size_t o = (size_t)(n0 + r) * K + k0 + tx;
        oh[o] = hi; ol[o] = lo;
    }
}

// ---------------------------------------------------------------------------
// Gather-GEMM (mma.sync, 2-term bf16 split).
// MODE 1: t[tok, e*256+n] = (x[tok] @ w1[e]) * mw     (grid 2 x MAXT1)
// MODE 2: h[tok, n] = gelu(t[tok, pair-K] @ w2slice)  (grid 32 x MAXT2)
// MODE 3: out = h @ lin2 + b (dense)                  (grid 8 x 64)
// ---------------------------------------------------------------------------
template <int MODE>
__global__ void __launch_bounds__(NTHREADS, 2)
mma_gemm(const float* __restrict__ bias, float* __restrict__ Cf) {
    __shared__ int ts[128];
    __shared__ float smw[128];
    extern __shared__ char smem[];
    const uint32_t sbase = s2u(smem);
    const int tid = threadIdx.x;
    const int lane = tid & 31;
    const int wid = tid >> 5;
    const int wm = wid & 3;
    const int wn = wid >> 2;

    int nrows = 128;
    int e = 0, e0 = 0, e1 = 0;
    if (MODE == 1) {
        if ((int)blockIdx.y >= g_meta[0]) return;
        e = g_t1grp[blockIdx.y];
        int r0 = g_t1row[blockIdx.y];
        nrows = min(128, g_ecnt[e] - r0);
        if (tid < 128) {
            int idx = g_eoff[e] + r0 + ((tid < nrows) ? tid : 0);
            int tk = g_etok[idx];
            ts[tid] = tk;
            smw[tid] = g_mw[tk * NE + e];
        }
    } else if (MODE == 2) {
        if ((int)blockIdx.y >= g_meta[1]) return;
        int p = g_t2grp[blockIdx.y];
        int r0 = g_t2row[blockIdx.y];
        nrows = min(128, g_pcnt[p] - r0);
        e0 = g_pe0[p]; e1 = g_pe1[p];
        if (tid < 128)
            ts[tid] = g_ptok[g_poff[p] + r0 + ((tid < nrows) ? tid : 0)];
    } else {
        if (tid < 128) ts[tid] = blockIdx.y * 128 + tid;
    }
    __syncthreads();

    // operand bases
    const __nv_bfloat16 *Ahp, *Alp, *Bhp, *Blp;
    int ldA, ldB, brow0, NC;
    if (MODE == 1) {
        Ahp = g_xh; Alp = g_xl; ldA = HID;
        Bhp = g_w1h; Blp = g_w1l; ldB = HID;
        brow0 = e * 256 + blockIdx.x * 128;
        NC = HID / 32;
    } else if (MODE == 2) {
        Ahp = g_th; Alp = g_tl; ldA = ERK;
        Bhp = g_w2h; Blp = g_w2l; ldB = ERK;
        brow0 = blockIdx.x * 128;
        NC = 512 / 32;
    } else {
        Ahp = g_hh; Alp = g_hl; ldA = FFN;
        Bhp = g_w3h; Blp = g_w3l; ldB = FFN;
        brow0 = blockIdx.x * 128;
        NC = FFN / 32;
    }

    const int r0s = tid >> 2, q0 = tid & 3;
    const int r1s = r0s + 64;
    const size_t aoff0 = (size_t)ts[r0s] * ldA;
    const size_t aoff1 = (size_t)ts[r1s] * ldA;
    const size_t boff0 = (size_t)(brow0 + r0s) * ldB;
    const size_t boff1 = (size_t)(brow0 + r1s) * ldB;

    float acc[2][8][4];
#pragma unroll
    for (int i = 0; i < 2; i++)
#pragma unroll
        for (int j = 0; j < 8; j++)
#pragma unroll
            for (int k = 0; k < 4; k++) acc[i][j][k] = 0.f;

    auto kseg = [&](int c) -> size_t {
        if (MODE == 2)
            return (c < 8) ? (size_t)e0 * 256 + (size_t)c * 32
                           : (size_t)e1 * 256 + (size_t)(c - 8) * 32;
        return (size_t)c * 32;
    };

    auto load_chunk = [&](int c, int st) {
        const size_t ko = kseg(c);
        const uint32_t s = sbase + (uint32_t)st * STAGEB;
        uint32_t d0 = s + (uint32_t)(r0s * ROWB + q0 * 16);
        uint32_t d1 = s + (uint32_t)(r1s * ROWB + q0 * 16);
        const size_t qo = (size_t)q0 * 8;
        cp16(d0,             Ahp + aoff0 + ko + qo);
        cp16(d0 + TILEB,     Alp + aoff0 + ko + qo);
        cp16(d0 + 2*TILEB,   Bhp + boff0 + ko + qo);
        cp16(d0 + 3*TILEB,   Blp + boff0 + ko + qo);
        cp16(d1,             Ahp + aoff1 + ko + qo);
        cp16(d1 + TILEB,     Alp + aoff1 + ko + qo);
        cp16(d1 + 2*TILEB,   Bhp + boff1 + ko + qo);
        cp16(d1 + 3*TILEB,   Blp + boff1 + ko + qo);
        cp_commit();
    };

    load_chunk(0, 0);

    const int g = lane >> 3, lr = lane & 7;

    for (int c = 0; c < NC; c++) {
        cp_wait<0>();
        __syncthreads();
        if (c + 1 < NC) load_chunk(c + 1, (c + 1) & 1);

        const uint32_t s0 = sbase + (uint32_t)((c & 1) * STAGEB);
#pragma unroll
        for (int ks = 0; ks < 2; ks++) {
            uint32_t afh[2][4], afl[2][4];
#pragma unroll
            for (int mt = 0; mt < 2; mt++) {
                int row = wm * 32 + mt * 16 + (g & 1) * 8 + lr;
                uint32_t addr = s0 + (uint32_t)(row * ROWB + ks * 32 + (g >> 1) * 16);
                ldsm4(afh[mt], addr);
                ldsm4(afl[mt], addr + TILEB);
            }
#pragma unroll
            for (int np = 0; np < 4; np++) {
                uint32_t bfh[4], bfl[4];
                int row = wn * 64 + np * 16 + (g >> 1) * 8 + lr;
                uint32_t addr = s0 + (uint32_t)(2*TILEB + row * ROWB + ks * 32 + (g & 1) * 16);
                ldsm4(bfh, addr);
                ldsm4(bfl, addr + TILEB);
#pragma unroll
                for (int mt = 0; mt < 2; mt++) {
#pragma unroll
                    for (int h2 = 0; h2 < 2; h2++) {
                        float* cc = acc[mt][np * 2 + h2];
                        mma16816(cc, afh[mt], bfh + h2 * 2);
                        mma16816(cc, afh[mt], bfl + h2 * 2);
                        mma16816(cc, afl[mt], bfh + h2 * 2);
                    }
                }
            }
        }
    }

    // Epilogue
#pragma unroll
    for (int mt = 0; mt < 2; mt++) {
#pragma unroll
        for (int half = 0; half < 2; half++) {
            const int rl = wm * 32 + mt * 16 + half * 8 + (lane >> 2);
            const bool valid = rl < nrows;
            const int tok = ts[rl];
            float s = 1.f;
            if (MODE == 1) s = smw[rl];
            size_t rbase;
            if (MODE == 1)      rbase = (size_t)tok * ERK + e * 256 + blockIdx.x * 128;
            else if (MODE == 2) rbase = (size_t)tok * FFN + blockIdx.x * 128;
            else                rbase = (size_t)tok * HID + blockIdx.x * 128;
#pragma unroll
            for (int nt = 0; nt < 8; nt++) {
                const int col = wn * 64 + nt * 8 + (lane & 3) * 2;
                float v0 = acc[mt][nt][half * 2 + 0];
                float v1 = acc[mt][nt][half * 2 + 1];
                if (MODE == 3) {
                    if (valid) {
                        float2 o;
                        o.x = v0 + bias[blockIdx.x * 128 + col];
                        o.y = v1 + bias[blockIdx.x * 128 + col + 1];
                        *reinterpret_cast<float2*>(Cf + rbase + col) = o;
                    }
                } else {
                    if (MODE == 1) { v0 *= s; v1 *= s; }
                    else {
                        v0 = 0.5f * v0 * (1.f + erff(v0 * 0.70710678118654752f));
                        v1 = 0.5f * v1 * (1.f + erff(v1 * 0.70710678118654752f));
                    }
                    if (valid) {
                        __nv_bfloat16 h0, h1, l0, l1;
                        split_bf16(v0, h0, l0); split_bf16(v1, h1, l1);
                        __nv_bfloat162 hp; hp.x = h0; hp.y = h1;
                        __nv_bfloat162 lp; lp.x = l0; lp.y = l1;
                        __nv_bfloat16* Ch = (MODE == 1) ? g_th : g_hh;
                        __nv_bfloat16* Cl = (MODE == 1) ? g_tl : g_hl;
                        *reinterpret_cast<__nv_bfloat162*>(Ch + rbase + col) = hp;
                        *reinterpret_cast<__nv_bfloat162*>(Cl + rbase + col) = lp;
                    }
                }
            }
        }
    }
}

// ---------------------------------------------------------------------------
extern "C" void kernel_launch(void* const* d_in, const int* in_sizes, int n_in,
                              void* d_out, int out_size) {
    const float* x        = (const float*)d_in[0];
    const float* router_w = (const float*)d_in[1];
    const float* router_b = (const float*)d_in[2];
    const float* w1       = (const float*)d_in[3];
    const float* w2       = (const float*)d_in[4];
    const float* lin2_w   = (const float*)d_in[5];
    const float* lin2_b   = (const float*)d_in[6];
    float* out = (float*)d_out;

    __nv_bfloat16 *xh, *xl, *w1h, *w1l, *w2h, *w2l, *w3h, *w3l;
    cudaGetSymbolAddress((void**)&xh, g_xh);   cudaGetSymbolAddress((void**)&xl, g_xl);
    cudaGetSymbolAddress((void**)&w1h, g_w1h); cudaGetSymbolAddress((void**)&w1l, g_w1l);
    cudaGetSymbolAddress((void**)&w2h, g_w2h); cudaGetSymbolAddress((void**)&w2l, g_w2l);
    cudaGetSymbolAddress((void**)&w3h, g_w3h); cudaGetSymbolAddress((void**)&w3l, g_w3l);

    cudaFuncSetAttribute(mma_gemm<1>, cudaFuncAttributeMaxDynamicSharedMemorySize, SMEM_BYTES);
    cudaFuncSetAttribute(mma_gemm<2>, cudaFuncAttributeMaxDynamicSharedMemorySize, SMEM_BYTES);
    cudaFuncSetAttribute(mma_gemm<3>, cudaFuncAttributeMaxDynamicSharedMemorySize, SMEM_BYTES);

    // Routing metadata
    zero_kernel<<<1, 32>>>();
    router_kernel<<<TOK / 8, 256>>>(x, router_w, router_b);
    plan_kernel<<<1, 1>>>();
    scatter_kernel<<<TOK / 256, 256>>>();

    // Conversions
    convert_x_kernel<<<(TOK * HID / 4) / 256, 256>>>(x, xh, xl);
    convert_w_kernel<<<dim3(RNK / 32, HID / 32, NE), dim3(32, 8)>>>(
        w1, w1h, w1l, HID, RNK, (size_t)HID * RNK, (size_t)RNK * HID);
    convert_w_kernel<<<dim3(FFN / 32, ERK / 32, 1), dim3(32, 8)>>>(
        w2, w2h, w2l, ERK, FFN, 0, 0);
    convert_w_kernel<<<dim3(HID / 32, FFN / 32, 1), dim3(32, 8)>>>(
        lin2_w, w3h, w3l, FFN, HID, 0, 0);

    // Stage 1 (sparse, per-expert): t = (x @ w1[e]) * mw
    mma_gemm<1><<<dim3(2, MAXT1), NTHREADS, SMEM_BYTES>>>(nullptr, nullptr);
    // Stage 2 (sparse, per-pair, K=512): h = gelu(t @ w2)
    mma_gemm<2><<<dim3(FFN / 128, MAXT2), NTHREADS, SMEM_BYTES>>>(nullptr, nullptr);
    // Stage 3 (dense): out = h @ lin2 + b
    mma_gemm<3><<<dim3(HID / 128, TOK / 128), NTHREADS, SMEM_BYTES>>>(lin2_b, out);
}